// round 1
// baseline (speedup 1.0000x reference)
#include <cuda_runtime.h>
#include <cstddef>

// ---------------------------------------------------------------------------
// Problem: out[b,c,s,h,j] = sum_{t=-64..64} bank[s][t+64] * x[b,c,h,j+t]
//   x: [8,16,128,1024] f32, out: [8,16,4,128,1024] f32, x==0 outside [0,1024)
//   bank[s][k] = exp(-0.5*((k-64)/s)^2) * cos(5*(k-64)/s) / sqrt(s)
// ---------------------------------------------------------------------------

constexpr int WIDTH  = 1024;
constexpr int HALF   = 64;
constexpr int KTAPS  = 129;
constexpr int NSCALE = 4;
constexpr int SMN    = WIDTH + 2 * HALF;   // 1152 floats staged in smem
constexpr int T      = 8;                  // outputs per thread
constexpr int NTHR   = WIDTH / T;          // 128 threads per row
constexpr int NROWS  = 8 * 16 * 128;       // 16384 rows

// ---------------- constexpr math (compile-time wavelet bank) ----------------

__host__ __device__ constexpr double cexp_taylor(double x) {
    double term = 1.0, sum = 1.0;
    for (int n = 1; n <= 26; ++n) { term = term * x / (double)n; sum += term; }
    return sum;
}
__host__ __device__ constexpr double cexp(double x) {
    double y = x; int halvings = 0;
    while (y > 0.25 || y < -0.25) { y *= 0.5; ++halvings; }
    double r = cexp_taylor(y);
    for (int i = 0; i < halvings; ++i) r *= r;
    return r;
}
__host__ __device__ constexpr double ccos(double x) {
    double y = x < 0.0 ? -x : x;
    const double TWO_PI = 6.283185307179586476925286766559;
    const double PI     = 3.141592653589793238462643383280;
    long long k = (long long)(y / TWO_PI);
    y -= (double)k * TWO_PI;
    if (y > PI) y = TWO_PI - y;
    double x2 = y * y, term = 1.0, sum = 1.0;
    for (int n = 1; n <= 16; ++n) {
        term *= -x2 / ((2.0 * n - 1.0) * (2.0 * n));
        sum += term;
    }
    return sum;
}

struct Bank { float c[NSCALE][KTAPS]; };

__host__ __device__ constexpr Bank make_bank() {
    Bank b{};
    const double scales[NSCALE]   = {2.0, 4.0, 8.0, 16.0};
    const double inv_sqrt[NSCALE] = {0.70710678118654752440, 0.5,
                                     0.35355339059327376220, 0.25};
    for (int s = 0; s < NSCALE; ++s) {
        for (int k = 0; k < KTAPS; ++k) {
            double t = (double)(k - HALF);
            double z = t / scales[s];
            double v = cexp(-0.5 * z * z) * ccos(5.0 * z) * inv_sqrt[s];
            double av = v < 0.0 ? -v : v;
            // Truncate negligible taps (error ~1e-5 abs << 1e-3 gate) so the
            // dead FMAs are eliminated at compile time.
            b.c[s][k] = (av < 1e-6) ? 0.0f : (float)v;
        }
    }
    return b;
}

// ------------------------------- kernel -------------------------------------

__global__ void __launch_bounds__(NTHR)
cwt_kernel(const float* __restrict__ x, float* __restrict__ out) {
    constexpr Bank BK = make_bank();

    __shared__ float sm[SMN];

    const int row = blockIdx.x;          // 0 .. NROWS-1  == (b*C + c)*H + h
    const int tid = threadIdx.x;

    // Stage one padded row into shared memory: sm[HALF + j] = x_row[j]
    const float4* xv = reinterpret_cast<const float4*>(x + (size_t)row * WIDTH);
    float4*       sv = reinterpret_cast<float4*>(sm + HALF);
    if (tid < HALF) { sm[tid] = 0.0f; sm[SMN - HALF + tid] = 0.0f; }
#pragma unroll
    for (int i = tid; i < WIDTH / 4; i += NTHR) sv[i] = xv[i];
    __syncthreads();

    const int j0 = tid * T;              // first output index for this thread

    float acc[NSCALE][T];
#pragma unroll
    for (int s = 0; s < NSCALE; ++s)
#pragma unroll
        for (int u = 0; u < T; ++u) acc[s][u] = 0.0f;

    // Sliding window: input position i covers x[j0 + i - HALF].
    // Contribution to output (j0+u) uses tap index k = i - u.
    const float* base = sm + j0;
#pragma unroll
    for (int i4 = 0; i4 < (T + 2 * HALF) / 4; ++i4) {
        const float4 v = *reinterpret_cast<const float4*>(base + 4 * i4);
        const float xs[4] = {v.x, v.y, v.z, v.w};
#pragma unroll
        for (int q = 0; q < 4; ++q) {
            const int   i  = 4 * i4 + q;
            const float xi = xs[q];
#pragma unroll
            for (int s = 0; s < NSCALE; ++s) {
#pragma unroll
                for (int u = 0; u < T; ++u) {
                    const int k = i - u;
                    if (k >= 0 && k < KTAPS) {
                        const float cc = BK.c[s][k];   // compile-time constant
                        if (cc != 0.0f)
                            acc[s][u] = fmaf(xi, cc, acc[s][u]);
                    }
                }
            }
        }
    }

    // out layout: [B, C, S, H, W]; row = bc*H + h
    const int h  = row & (128 - 1);
    const int bc = row >> 7;
#pragma unroll
    for (int s = 0; s < NSCALE; ++s) {
        float* op = out + ((((size_t)bc * NSCALE + s) * 128 + h) * WIDTH) + j0;
        float4 a0 = make_float4(acc[s][0], acc[s][1], acc[s][2], acc[s][3]);
        float4 a1 = make_float4(acc[s][4], acc[s][5], acc[s][6], acc[s][7]);
        *reinterpret_cast<float4*>(op)     = a0;
        *reinterpret_cast<float4*>(op + 4) = a1;
    }
}

// ----------------------------- launch wrapper -------------------------------

extern "C" void kernel_launch(void* const* d_in, const int* in_sizes, int n_in,
                              void* d_out, int out_size) {
    (void)in_sizes; (void)n_in; (void)out_size;
    const float* x   = (const float*)d_in[0];
    float*       out = (float*)d_out;
    cwt_kernel<<<NROWS, NTHR>>>(x, out);
}

// round 2
// speedup vs baseline: 1.0039x; 1.0039x over previous
#include <cuda_runtime.h>
#include <cstddef>

// ---------------------------------------------------------------------------
// Problem: out[b,c,s,h,j] = sum_{t=-64..64} bank[s][t+64] * x[b,c,h,j+t]
//   x: [8,16,128,1024] f32, out: [8,16,4,128,1024] f32, x==0 outside [0,1024)
//   bank[s][k] = exp(-0.5*((k-64)/s)^2) * cos(5*(k-64)/s) / sqrt(s)
// ---------------------------------------------------------------------------

constexpr int WIDTH  = 1024;
constexpr int HALF   = 64;
constexpr int KTAPS  = 129;
constexpr int NSCALE = 4;
constexpr int SMN    = WIDTH + 2 * HALF;   // 1152 floats staged in smem
constexpr int T      = 8;                  // outputs per thread
constexpr int NTHR   = WIDTH / T;          // 128 threads per row
constexpr int NROWS  = 8 * 16 * 128;       // 16384 rows

// ---------------- constexpr math (compile-time wavelet bank) ----------------

__host__ __device__ constexpr double cexp_taylor(double x) {
    double term = 1.0, sum = 1.0;
    for (int n = 1; n <= 26; ++n) { term = term * x / (double)n; sum += term; }
    return sum;
}
__host__ __device__ constexpr double cexp(double x) {
    double y = x; int halvings = 0;
    while (y > 0.25 || y < -0.25) { y *= 0.5; ++halvings; }
    double r = cexp_taylor(y);
    for (int i = 0; i < halvings; ++i) r *= r;
    return r;
}
__host__ __device__ constexpr double ccos(double x) {
    double y = x < 0.0 ? -x : x;
    const double TWO_PI = 6.283185307179586476925286766559;
    const double PI     = 3.141592653589793238462643383280;
    long long k = (long long)(y / TWO_PI);
    y -= (double)k * TWO_PI;
    if (y > PI) y = TWO_PI - y;
    double x2 = y * y, term = 1.0, sum = 1.0;
    for (int n = 1; n <= 16; ++n) {
        term *= -x2 / ((2.0 * n - 1.0) * (2.0 * n));
        sum += term;
    }
    return sum;
}

struct Bank { float c[NSCALE][KTAPS]; };

__host__ __device__ constexpr Bank make_bank() {
    Bank b{};
    const double scales[NSCALE]   = {2.0, 4.0, 8.0, 16.0};
    const double inv_sqrt[NSCALE] = {0.70710678118654752440, 0.5,
                                     0.35355339059327376220, 0.25};
    for (int s = 0; s < NSCALE; ++s) {
        for (int k = 0; k < KTAPS; ++k) {
            double t = (double)(k - HALF);
            double z = t / scales[s];
            double v = cexp(-0.5 * z * z) * ccos(5.0 * z) * inv_sqrt[s];
            double av = v < 0.0 ? -v : v;
            // Truncate negligible taps (error ~1e-5 abs << 1e-3 gate) so the
            // dead FMAs are eliminated at compile time.
            b.c[s][k] = (av < 1e-6) ? 0.0f : (float)v;
        }
    }
    return b;
}

// ------------------------------- kernel -------------------------------------

__global__ void __launch_bounds__(NTHR)
cwt_kernel(const float* __restrict__ x, float* __restrict__ out) {
    constexpr Bank BK = make_bank();

    __shared__ float sm[SMN];

    const int row = blockIdx.x;          // 0 .. NROWS-1  == (b*C + c)*H + h
    const int tid = threadIdx.x;

    // Stage one padded row into shared memory: sm[HALF + j] = x_row[j]
    const float4* xv = reinterpret_cast<const float4*>(x + (size_t)row * WIDTH);
    float4*       sv = reinterpret_cast<float4*>(sm + HALF);
    if (tid < HALF) { sm[tid] = 0.0f; sm[SMN - HALF + tid] = 0.0f; }
#pragma unroll
    for (int i = tid; i < WIDTH / 4; i += NTHR) sv[i] = xv[i];
    __syncthreads();

    const int j0 = tid * T;              // first output index for this thread

    float acc[NSCALE][T];
#pragma unroll
    for (int s = 0; s < NSCALE; ++s)
#pragma unroll
        for (int u = 0; u < T; ++u) acc[s][u] = 0.0f;

    // Sliding window: input position i covers x[j0 + i - HALF].
    // Contribution to output (j0+u) uses tap index k = i - u.
    const float* base = sm + j0;
#pragma unroll
    for (int i4 = 0; i4 < (T + 2 * HALF) / 4; ++i4) {
        const float4 v = *reinterpret_cast<const float4*>(base + 4 * i4);
        const float xs[4] = {v.x, v.y, v.z, v.w};
#pragma unroll
        for (int q = 0; q < 4; ++q) {
            const int   i  = 4 * i4 + q;
            const float xi = xs[q];
#pragma unroll
            for (int s = 0; s < NSCALE; ++s) {
#pragma unroll
                for (int u = 0; u < T; ++u) {
                    const int k = i - u;
                    if (k >= 0 && k < KTAPS) {
                        const float cc = BK.c[s][k];   // compile-time constant
                        if (cc != 0.0f)
                            acc[s][u] = fmaf(xi, cc, acc[s][u]);
                    }
                }
            }
        }
    }

    // out layout: [B, C, S, H, W]; row = bc*H + h
    const int h  = row & (128 - 1);
    const int bc = row >> 7;
#pragma unroll
    for (int s = 0; s < NSCALE; ++s) {
        float* op = out + ((((size_t)bc * NSCALE + s) * 128 + h) * WIDTH) + j0;
        float4 a0 = make_float4(acc[s][0], acc[s][1], acc[s][2], acc[s][3]);
        float4 a1 = make_float4(acc[s][4], acc[s][5], acc[s][6], acc[s][7]);
        *reinterpret_cast<float4*>(op)     = a0;
        *reinterpret_cast<float4*>(op + 4) = a1;
    }
}

// ----------------------------- launch wrapper -------------------------------

extern "C" void kernel_launch(void* const* d_in, const int* in_sizes, int n_in,
                              void* d_out, int out_size) {
    (void)in_sizes; (void)n_in; (void)out_size;
    const float* x   = (const float*)d_in[0];
    float*       out = (float*)d_out;
    cwt_kernel<<<NROWS, NTHR>>>(x, out);
}